// round 14
// baseline (speedup 1.0000x reference)
#include <cuda_runtime.h>

#define TT 336

// ---------------- device scratch ----------------
__device__ float dW1g[2 * 80 * 280];        // [dir][k][up(35)][gate(4)][2], i/f/o prescaled 0.5
__device__ float dB1g[2 * 280];             // [dir][up][gate][2]
__device__ float dW2g[2 * 168 * 88];        // [dir][k(168 pad)][up(11)][gate(4)][2]
__device__ float dB2g[2 * 88];
__device__ float dH1T[64 * 336 * 140 * 32]; // [bblk][t][k(140)][r(32)]
__device__ float dH2[64 * 336 * 42 * 32];   // [bblk][t][u(42)][r(32)]

typedef unsigned long long ull;

// ---------------- f32x2 helpers ----------------
__device__ __forceinline__ ull pk2(float v) {
    ull r;
    asm("mov.b64 %0, {%1, %1};" : "=l"(r) : "f"(v));
    return r;
}
__device__ __forceinline__ float2 up2(ull v) {
    float2 r;
    asm("mov.b64 {%0, %1}, %2;" : "=f"(r.x), "=f"(r.y) : "l"(v));
    return r;
}
__device__ __forceinline__ void fma2(ull& d, ull a, ull b) {
    asm("fma.rn.f32x2 %0, %1, %2, %3;" : "=l"(d) : "l"(a), "l"(b), "l"(d));
}
__device__ __forceinline__ float tanha(float x) {
    float y;
    asm("tanh.approx.f32 %0, %1;" : "=f"(y) : "f"(x));
    return y;
}
// i/f/o pre-acts prescaled by 0.5 -> sigmoid(z) = 0.5 + 0.5*tanh(z/2)
__device__ __forceinline__ void lstm_act(float2 yi, float2 yf, float2 yg, float2 yo,
                                         float2& c, float2& h) {
    float six = 0.5f + 0.5f * tanha(yi.x), siy = 0.5f + 0.5f * tanha(yi.y);
    float sfx = 0.5f + 0.5f * tanha(yf.x), sfy = 0.5f + 0.5f * tanha(yf.y);
    float tgx = tanha(yg.x), tgy = tanha(yg.y);
    float sox = 0.5f + 0.5f * tanha(yo.x), soy = 0.5f + 0.5f * tanha(yo.y);
    c.x = sfx * c.x + six * tgx;
    c.y = sfy * c.y + siy * tgy;
    h.x = sox * tanha(c.x);
    h.y = soy * tanha(c.y);
}

// ---------------- weight prep ----------------
__global__ void prep1(const float* wfih, const float* wfhh, const float* bfih, const float* bfhh,
                      const float* wbih, const float* wbhh, const float* bbih, const float* bbhh) {
    int idx = blockIdx.x * blockDim.x + threadIdx.x;
    if (idx < 2 * 80 * 280) {
        int d = idx / 22400, rem = idx % 22400;
        int k = rem / 280, j = rem % 280;
        int up = j / 8, g = (j / 2) % 4, e = j & 1;
        int u = up * 2 + e, row = g * 70 + u;
        const float* wih = d ? wbih : wfih;
        const float* whh = d ? wbhh : wfhh;
        float v = (k < 10) ? wih[row * 10 + k] : whh[row * 70 + (k - 10)];
        if (g != 2) v *= 0.5f;
        dW1g[idx] = v;
    }
    if (idx < 2 * 280) {
        int d = idx / 280, j = idx % 280;
        int up = j / 8, g = (j / 2) % 4, e = j & 1;
        int u = up * 2 + e, row = g * 70 + u;
        const float* bih = d ? bbih : bfih;
        const float* bhh = d ? bbhh : bfhh;
        float v = bih[row] + bhh[row];
        if (g != 2) v *= 0.5f;
        dB1g[idx] = v;
    }
}

__global__ void prep2(const float* wfih, const float* wfhh, const float* bfih, const float* bfhh,
                      const float* wbih, const float* wbhh, const float* bbih, const float* bbhh) {
    int idx = blockIdx.x * blockDim.x + threadIdx.x;
    if (idx < 2 * 168 * 88) {
        int d = idx / 14784, rem = idx % 14784;
        int k = rem / 88, j = rem % 88;
        int up = j / 8, g = (j / 2) % 4, e = j & 1;
        int u = up * 2 + e;
        float v = 0.f;
        if (u < 21 && k < 161) {
            int row = g * 21 + u;
            const float* wih = d ? wbih : wfih;
            const float* whh = d ? wbhh : wfhh;
            v = (k < 140) ? wih[row * 140 + k] : whh[row * 21 + (k - 140)];
            if (g != 2) v *= 0.5f;
        }
        dW2g[idx] = v;
    }
    if (idx < 2 * 88) {
        int d = idx / 88, j = idx % 88;
        int up = j / 8, g = (j / 2) % 4, e = j & 1;
        int u = up * 2 + e;
        float v = 0.f;
        if (u < 21) {
            int row = g * 21 + u;
            const float* bih = d ? bbih : bfih;
            const float* bhh = d ? bbhh : bfhh;
            v = bih[row] + bhh[row];
            if (g != 2) v *= 0.5f;
        }
        dB2g[idx] = v;
    }
}

// ---------------- layer 1: F=10 -> H=70, bidirectional ----------------
// grid (64, 2), 280 threads = 2 k-groups x 140 (rg 0..3 [8 rows] x up 0..34).
// 8 rows/thread: 4 LDS.128 per 32 FFMA2 (LSU floor is the binding resource).
// Thread owns 4 of its 8 rows (grp0: j0..3, grp1: j4..7); single donor per row.
__global__ __launch_bounds__(280, 1) void lstm1(const float* __restrict__ x) {
    extern __shared__ float sm[];
    float* sW = sm;                  // 22400
    float* sB = sW + 22400;          // 280
    float* sA = sB + 280;            // 2 * 2560  ([k80][r32] per buffer)
    float* sRed = sA + 5120;         // [j8][gp2][q140][4] = 8960
    const int dir = blockIdx.y, bblk = blockIdx.x;
    const int b0 = bblk * 32;
    const int tid = threadIdx.x;

    const float* gW = dW1g + dir * 22400;
    for (int i = tid; i < 22400; i += 280) sW[i] = gW[i];
    sB[tid] = dB1g[dir * 280 + tid];
    for (int i = tid; i < 70 * 32; i += 280) sA[10 * 32 + i] = 0.f;   // h-region buf0

    const int grp = tid / 140;
    const int q = tid % 140;
    const int rg = q & 3, up = q >> 2;
    const int r0 = rg * 8, u0 = up * 2;
    const int jo = grp * 4;          // owned j: jo..jo+3
    const int jn = 4 - jo;           // donated j: jn..jn+3
    const int rown = r0 + jo;

    // x staging (320 slots over 280 threads)
    const int xrow0 = tid / 10, xf0 = tid % 10;
    const int i1 = tid + 280;
    const bool has1 = i1 < 320;
    const int xrow1 = i1 / 10, xf1 = i1 % 10;
    {
        int t0 = dir ? TT - 1 : 0;
        sA[xf0 * 32 + xrow0] = x[((b0 + xrow0) * TT + t0) * 10 + xf0];
        if (has1) sA[xf1 * 32 + xrow1] = x[((b0 + xrow1) * TT + t0) * 10 + xf1];
    }
    float xr0, xr1 = 0.f;
    {
        int t1 = dir ? TT - 2 : 1;
        xr0 = x[((b0 + xrow0) * TT + t1) * 10 + xf0];
        if (has1) xr1 = x[((b0 + xrow1) * TT + t1) * 10 + xf1];
    }

    float2 c[4];
#pragma unroll
    for (int r = 0; r < 4; r++) c[r] = make_float2(0.f, 0.f);
    const float* pw = sW + grp * 40 * 280 + up * 8;
    __syncthreads();

    float2 bf[4];
#pragma unroll
    for (int g = 0; g < 4; g++) bf[g] = *(const float2*)&sB[up * 8 + g * 2];

    int p = 0;
    for (int s = 0; s < TT; s++) {
        const int t = dir ? TT - 1 - s : s;
        const float* pa = sA + p * 2560 + grp * 1280 + r0;

        ull acc[8][4];
#pragma unroll
        for (int r = 0; r < 8; r++)
#pragma unroll
            for (int g = 0; g < 4; g++) acc[r][g] = 0ull;

#pragma unroll 5
        for (int k = 0; k < 40; k++) {
            float4 av0 = *(const float4*)(pa + k * 32);         // rows r0..r0+3
            float4 av1 = *(const float4*)(pa + k * 32 + 4);     // rows r0+4..r0+7
            ull a0 = pk2(av0.x), a1 = pk2(av0.y), a2 = pk2(av0.z), a3 = pk2(av0.w);
            ull a4 = pk2(av1.x), a5 = pk2(av1.y), a6 = pk2(av1.z), a7 = pk2(av1.w);
            ulonglong2 w01 = *(const ulonglong2*)(pw + k * 280);
            ulonglong2 w23 = *(const ulonglong2*)(pw + k * 280 + 4);
            fma2(acc[0][0], a0, w01.x); fma2(acc[0][1], a0, w01.y);
            fma2(acc[0][2], a0, w23.x); fma2(acc[0][3], a0, w23.y);
            fma2(acc[1][0], a1, w01.x); fma2(acc[1][1], a1, w01.y);
            fma2(acc[1][2], a1, w23.x); fma2(acc[1][3], a1, w23.y);
            fma2(acc[2][0], a2, w01.x); fma2(acc[2][1], a2, w01.y);
            fma2(acc[2][2], a2, w23.x); fma2(acc[2][3], a2, w23.y);
            fma2(acc[3][0], a3, w01.x); fma2(acc[3][1], a3, w01.y);
            fma2(acc[3][2], a3, w23.x); fma2(acc[3][3], a3, w23.y);
            fma2(acc[4][0], a4, w01.x); fma2(acc[4][1], a4, w01.y);
            fma2(acc[4][2], a4, w23.x); fma2(acc[4][3], a4, w23.y);
            fma2(acc[5][0], a5, w01.x); fma2(acc[5][1], a5, w01.y);
            fma2(acc[5][2], a5, w23.x); fma2(acc[5][3], a5, w23.y);
            fma2(acc[6][0], a6, w01.x); fma2(acc[6][1], a6, w01.y);
            fma2(acc[6][2], a6, w23.x); fma2(acc[6][3], a6, w23.y);
            fma2(acc[7][0], a7, w01.x); fma2(acc[7][1], a7, w01.y);
            fma2(acc[7][2], a7, w23.x); fma2(acc[7][3], a7, w23.y);
        }

        // donate non-owned 4 rows: 8 STS.128, q-coalesced
#pragma unroll
        for (int jj = 0; jj < 4; jj++) {
            int j = jn + jj;
            *(ulonglong2*)&sRed[((j * 2 + 0) * 140 + q) * 4] = make_ulonglong2(acc[j][0], acc[j][1]);
            *(ulonglong2*)&sRed[((j * 2 + 1) * 140 + q) * 4] = make_ulonglong2(acc[j][2], acc[j][3]);
        }
        __syncthreads();

        float2 hv[4];
#pragma unroll
        for (int jj = 0; jj < 4; jj++) {
            int j = jo + jj;
            ulonglong2 p01 = *(const ulonglong2*)&sRed[((j * 2 + 0) * 140 + q) * 4];
            ulonglong2 p23 = *(const ulonglong2*)&sRed[((j * 2 + 1) * 140 + q) * 4];
            float2 y0 = up2(acc[j][0]), d0 = up2(p01.x);
            float2 y1 = up2(acc[j][1]), d1 = up2(p01.y);
            float2 y2 = up2(acc[j][2]), d2 = up2(p23.x);
            float2 y3 = up2(acc[j][3]), d3 = up2(p23.y);
            y0.x += d0.x + bf[0].x; y0.y += d0.y + bf[0].y;
            y1.x += d1.x + bf[1].x; y1.y += d1.y + bf[1].y;
            y2.x += d2.x + bf[2].x; y2.y += d2.y + bf[2].y;
            y3.x += d3.x + bf[3].x; y3.y += d3.y + bf[3].y;
            lstm_act(y0, y1, y2, y3, c[jj], hv[jj]);
        }

        // h(t) -> other buffer: 2 STS.128 (4 rows each unit); global: 2 STG.128
        float* nb = sA + (p ^ 1) * 2560;
        *(float4*)&nb[(10 + u0) * 32 + rown] = make_float4(hv[0].x, hv[1].x, hv[2].x, hv[3].x);
        *(float4*)&nb[(11 + u0) * 32 + rown] = make_float4(hv[0].y, hv[1].y, hv[2].y, hv[3].y);
        {
            size_t gb = ((size_t)(bblk * TT + t) * 140 + dir * 70 + u0) * 32 + rown;
            *(float4*)&dH1T[gb]      = make_float4(hv[0].x, hv[1].x, hv[2].x, hv[3].x);
            *(float4*)&dH1T[gb + 32] = make_float4(hv[0].y, hv[1].y, hv[2].y, hv[3].y);
        }
        // stage x(t+1) + prefetch x(t+2)
        if (s + 1 < TT) {
            nb[xf0 * 32 + xrow0] = xr0;
            if (has1) nb[xf1 * 32 + xrow1] = xr1;
            if (s + 2 < TT) {
                int tn = dir ? TT - 3 - s : s + 2;
                xr0 = x[((b0 + xrow0) * TT + tn) * 10 + xf0];
                if (has1) xr1 = x[((b0 + xrow1) * TT + tn) * 10 + xf1];
            }
        }
        __syncthreads();
        p ^= 1;
    }
}

// ---------------- layer 2: 140 -> H=21 (pad 22), bidirectional ----------------
// grid (64, 2), 352 threads = 8 k-groups x 44 (rg 0..3 [8 rows] x up 0..10).
// k padded to 168 = 8*21: uniform 21-iter loop for all groups (zero-padded
// weights k>=161 and acts k in [161,168)) -> no divergent re-execution in warps
// straddling group boundaries. Each group owns row r0+grp; 7-donor reduction
// packed as STS.128/LDS.128.
// sRed float index: [row j(8)][slot(7)][gatepair(2)][q(44)][4]
#define SRED2(j, sl, gp, q) (((((j) * 7 + (sl)) * 2 + (gp)) * 44 + (q)) * 4)

__global__ __launch_bounds__(352, 1) void lstm2() {
    extern __shared__ float sm[];
    float* sW = sm;                  // 168*88 = 14784
    float* sB = sW + 14784;          // 88
    float* sA = sB + 88;             // 2 * 5376  ([k168][r32] per buffer)
    float* sRed = sA + 10752;        // 8*7*2*44*4 = 19712
    const int dir = blockIdx.y, bblk = blockIdx.x;
    const int tid = threadIdx.x;

    const float* gW = dW2g + dir * 14784;
    for (int i = tid; i < 14784; i += 352) sW[i] = gW[i];
    if (tid < 88) sB[tid] = dB2g[dir * 88 + tid];
    // zero h-region + k-pad for BOTH buffers (pad never rewritten; h rewritten per step)
    for (int i = tid; i < 28 * 32; i += 352) {
        sA[140 * 32 + i] = 0.f;
        sA[5376 + 140 * 32 + i] = 0.f;
    }

    // stage h1(t0): 1120 float4 contiguous
    {
        int t0 = dir ? TT - 1 : 0;
        const float4* src = (const float4*)&dH1T[(size_t)(bblk * TT + t0) * 4480];
        float4* dst = (float4*)sA;
#pragma unroll
        for (int j = 0; j < 4; j++) {
            int i = tid + j * 352;
            if (i < 1120) dst[i] = src[i];
        }
    }

    const int grp = tid / 44;
    const int q = tid - 44 * grp;
    const int rg = q & 3, up = q >> 2;
    const int r0 = rg * 8, u0 = up * 2;
    const int rown = r0 + grp;       // owned row

    float2 c = make_float2(0.f, 0.f);
    const int kbeg = grp * 21;
    const float* pw = sW + kbeg * 88 + up * 8;

    // prefetch h1(t1)
    float4 pf[4];
    {
        int t1 = dir ? TT - 2 : 1;
        const float4* src = (const float4*)&dH1T[(size_t)(bblk * TT + t1) * 4480];
#pragma unroll
        for (int j = 0; j < 4; j++) {
            int i = tid + j * 352;
            if (i < 1120) pf[j] = src[i];
        }
    }
    __syncthreads();

    float2 bf[4];
#pragma unroll
    for (int g = 0; g < 4; g++) bf[g] = *(const float2*)&sB[up * 8 + g * 2];

    int p = 0;
    for (int s = 0; s < TT; s++) {
        const int t = dir ? TT - 1 - s : s;
        const float* pa = sA + p * 5376 + kbeg * 32 + r0;

        ull acc[8][4];
#pragma unroll
        for (int r = 0; r < 8; r++)
#pragma unroll
            for (int g = 0; g < 4; g++) acc[r][g] = 0ull;

#pragma unroll 7
        for (int k = 0; k < 21; k++) {
            float4 av0 = *(const float4*)(pa + k * 32);
            float4 av1 = *(const float4*)(pa + k * 32 + 4);
            ull a0 = pk2(av0.x), a1 = pk2(av0.y), a2 = pk2(av0.z), a3 = pk2(av0.w);
            ull a4 = pk2(av1.x), a5 = pk2(av1.y), a6 = pk2(av1.z), a7 = pk2(av1.w);
            ulonglong2 w01 = *(const ulonglong2*)(pw + k * 88);
            ulonglong2 w23 = *(const ulonglong2*)(pw + k * 88 + 4);
            fma2(acc[0][0], a0, w01.x); fma2(acc[0][1], a0, w01.y);
            fma2(acc[0][2], a0, w23.x); fma2(acc[0][3], a0, w23.y);
            fma2(acc[1][0], a1, w01.x); fma2(acc[1][1], a1, w01.y);
            fma2(acc[1][2], a1, w23.x); fma2(acc[1][3], a1, w23.y);
            fma2(acc[2][0], a2, w01.x); fma2(acc[2][1], a2, w01.y);
            fma2(acc[2][2], a2, w23.x); fma2(acc[2][3], a2, w23.y);
            fma2(acc[3][0], a3, w01.x); fma2(acc[3][1], a3, w01.y);
            fma2(acc[3][2], a3, w23.x); fma2(acc[3][3], a3, w23.y);
            fma2(acc[4][0], a4, w01.x); fma2(acc[4][1], a4, w01.y);
            fma2(acc[4][2], a4, w23.x); fma2(acc[4][3], a4, w23.y);
            fma2(acc[5][0], a5, w01.x); fma2(acc[5][1], a5, w01.y);
            fma2(acc[5][2], a5, w23.x); fma2(acc[5][3], a5, w23.y);
            fma2(acc[6][0], a6, w01.x); fma2(acc[6][1], a6, w01.y);
            fma2(acc[6][2], a6, w23.x); fma2(acc[6][3], a6, w23.y);
            fma2(acc[7][0], a7, w01.x); fma2(acc[7][1], a7, w01.y);
            fma2(acc[7][2], a7, w23.x); fma2(acc[7][3], a7, w23.y);
        }

        // donate 7 non-owned rows: 14 STS.128 (q-coalesced)
#pragma unroll
        for (int j = 0; j < 8; j++) {
            if (j != grp) {
                int sl = grp - ((grp > j) ? 1 : 0);
                *(ulonglong2*)&sRed[SRED2(j, sl, 0, q)] = make_ulonglong2(acc[j][0], acc[j][1]);
                *(ulonglong2*)&sRed[SRED2(j, sl, 1, q)] = make_ulonglong2(acc[j][2], acc[j][3]);
            }
        }
        __syncthreads();

        // finalize owned row: own + 7 donors + bias
        float2 y[4];
#pragma unroll
        for (int g = 0; g < 4; g++) y[g] = up2(acc[grp][g]);
#pragma unroll
        for (int sl = 0; sl < 7; sl++) {
            ulonglong2 p01 = *(const ulonglong2*)&sRed[SRED2(grp, sl, 0, q)];
            ulonglong2 p23 = *(const ulonglong2*)&sRed[SRED2(grp, sl, 1, q)];
            float2 d0 = up2(p01.x), d1 = up2(p01.y), d2 = up2(p23.x), d3 = up2(p23.y);
            y[0].x += d0.x; y[0].y += d0.y;
            y[1].x += d1.x; y[1].y += d1.y;
            y[2].x += d2.x; y[2].y += d2.y;
            y[3].x += d3.x; y[3].y += d3.y;
        }
#pragma unroll
        for (int g = 0; g < 4; g++) { y[g].x += bf[g].x; y[g].y += bf[g].y; }
        float2 h;
        lstm_act(y[0], y[1], y[2], y[3], c, h);

        // h -> other buffer + global dH2 [bblk][t][42][r32] (coalesced)
        float* nb = sA + (p ^ 1) * 5376;
        nb[(140 + u0) * 32 + rown] = h.x;
        if (u0 + 1 < 21) nb[(141 + u0) * 32 + rown] = h.y;
        {
            size_t ob = ((size_t)(bblk * TT + t) * 42 + dir * 21 + u0) * 32 + rown;
            dH2[ob] = h.x;
            if (u0 + 1 < 21) dH2[ob + 32] = h.y;
        }

        // stage h1(t+1) into other buffer (contiguous STS.128)
        if (s + 1 < TT) {
            float4* dst = (float4*)nb;
#pragma unroll
            for (int j = 0; j < 4; j++) {
                int i = tid + j * 352;
                if (i < 1120) dst[i] = pf[j];
            }
        }
        // prefetch h1(t+2)
        if (s + 2 < TT) {
            int tn = dir ? TT - 3 - s : s + 2;
            const float4* src = (const float4*)&dH1T[(size_t)(bblk * TT + tn) * 4480];
#pragma unroll
            for (int j = 0; j < 4; j++) {
                int i = tid + j * 352;
                if (i < 1120) pf[j] = src[i];
            }
        }
        __syncthreads();
        p ^= 1;
    }
}

// ---------------- dense head: 42 -> relu 30 -> relu 20 -> 1 ----------------
__global__ __launch_bounds__(128) void dense_head(const float* __restrict__ wd1, const float* __restrict__ bd1,
                                                  const float* __restrict__ wd2, const float* __restrict__ bd2,
                                                  const float* __restrict__ wo, const float* __restrict__ bo,
                                                  float* __restrict__ out) {
    __shared__ float sT[4 * 42 * 32];
    __shared__ float sW1[30 * 42], sb1[30], sW2[20 * 30], sb2[20], swo[20], sbo[1];
    const int tid = threadIdx.x;
    const int bblk = blockIdx.x, t0 = blockIdx.y * 4;

    {
        const float4* src = (const float4*)&dH2[(size_t)(bblk * TT + t0) * 1344];
        float4* dst = (float4*)sT;
#pragma unroll
        for (int j = 0; j < 11; j++) {
            int i = tid + j * 128;
            if (i < 1344) dst[i] = src[i];
        }
    }
    for (int i = tid; i < 1260; i += 128) sW1[i] = wd1[i];
    for (int i = tid; i < 600; i += 128) sW2[i] = wd2[i];
    if (tid < 30) sb1[tid] = bd1[tid];
    if (tid < 20) { sb2[tid] = bd2[tid]; swo[tid] = wo[tid]; }
    if (tid == 0) sbo[0] = bo[0];
    __syncthreads();

    const int t = tid >> 5, r = tid & 31;
    float in[42];
#pragma unroll
    for (int u = 0; u < 42; u++) in[u] = sT[(t * 42 + u) * 32 + r];

    float a[30];
#pragma unroll
    for (int j = 0; j < 30; j++) {
        float s = sb1[j];
#pragma unroll
        for (int k = 0; k < 42; k++) s += in[k] * sW1[j * 42 + k];
        a[j] = fmaxf(s, 0.f);
    }
    float o = sbo[0];
#pragma unroll
    for (int j = 0; j < 20; j++) {
        float s = sb2[j];
#pragma unroll
        for (int k = 0; k < 30; k++) s += a[k] * sW2[j * 30 + k];
        o += fmaxf(s, 0.f) * swo[j];
    }
    out[(size_t)(bblk * 32 + r) * TT + t0 + t] = o;
}

// ---------------- launch ----------------
extern "C" void kernel_launch(void* const* d_in, const int* in_sizes, int n_in,
                              void* d_out, int out_size) {
    const float* x = (const float*)d_in[0];

    const int smem1 = (22400 + 280 + 2 * 2560 + 8960) * 4;    // 147040 B
    const int smem2 = (14784 + 88 + 2 * 5376 + 19712) * 4;    // 181344 B
    cudaFuncSetAttribute(lstm1, cudaFuncAttributeMaxDynamicSharedMemorySize, smem1);
    cudaFuncSetAttribute(lstm2, cudaFuncAttributeMaxDynamicSharedMemorySize, smem2);

    prep1<<<175, 256>>>((const float*)d_in[1], (const float*)d_in[2], (const float*)d_in[3], (const float*)d_in[4],
                        (const float*)d_in[5], (const float*)d_in[6], (const float*)d_in[7], (const float*)d_in[8]);
    prep2<<<116, 256>>>((const float*)d_in[9], (const float*)d_in[10], (const float*)d_in[11], (const float*)d_in[12],
                        (const float*)d_in[13], (const float*)d_in[14], (const float*)d_in[15], (const float*)d_in[16]);

    lstm1<<<dim3(64, 2), 280, smem1>>>(x);
    lstm2<<<dim3(64, 2), 352, smem2>>>();

    dense_head<<<dim3(64, 84), 128>>>((const float*)d_in[17], (const float*)d_in[18],
                                      (const float*)d_in[19], (const float*)d_in[20],
                                      (const float*)d_in[21], (const float*)d_in[22],
                                      (float*)d_out);
}

// round 15
// speedup vs baseline: 1.1778x; 1.1778x over previous
#include <cuda_runtime.h>

#define TT 336

// ---------------- device scratch ----------------
__device__ float dW1g[2 * 80 * 280];        // [dir][k][up(35)][gate(4)][2], i/f/o prescaled 0.5
__device__ float dB1g[2 * 280];             // [dir][up][gate][2]
__device__ float dW2g[2 * 161 * 88];        // [dir][k][up(11)][gate(4)][2]
__device__ float dB2g[2 * 88];
__device__ float dH1T[64 * 336 * 140 * 32]; // [bblk][t][k(140)][r(32)]
__device__ float dH2[64 * 336 * 42 * 32];   // [bblk][t][u(42)][r(32)]

typedef unsigned long long ull;

// ---------------- f32x2 helpers ----------------
__device__ __forceinline__ ull pk2(float v) {
    ull r;
    asm("mov.b64 %0, {%1, %1};" : "=l"(r) : "f"(v));
    return r;
}
__device__ __forceinline__ float2 up2(ull v) {
    float2 r;
    asm("mov.b64 {%0, %1}, %2;" : "=f"(r.x), "=f"(r.y) : "l"(v));
    return r;
}
__device__ __forceinline__ void fma2(ull& d, ull a, ull b) {
    asm("fma.rn.f32x2 %0, %1, %2, %3;" : "=l"(d) : "l"(a), "l"(b), "l"(d));
}
__device__ __forceinline__ float tanha(float x) {
    float y;
    asm("tanh.approx.f32 %0, %1;" : "=f"(y) : "f"(x));
    return y;
}
// i/f/o pre-acts prescaled by 0.5 -> sigmoid(z) = 0.5 + 0.5*tanh(z/2)
__device__ __forceinline__ void lstm_act(float2 yi, float2 yf, float2 yg, float2 yo,
                                         float2& c, float2& h) {
    float six = 0.5f + 0.5f * tanha(yi.x), siy = 0.5f + 0.5f * tanha(yi.y);
    float sfx = 0.5f + 0.5f * tanha(yf.x), sfy = 0.5f + 0.5f * tanha(yf.y);
    float tgx = tanha(yg.x), tgy = tanha(yg.y);
    float sox = 0.5f + 0.5f * tanha(yo.x), soy = 0.5f + 0.5f * tanha(yo.y);
    c.x = sfx * c.x + six * tgx;
    c.y = sfy * c.y + siy * tgy;
    h.x = sox * tanha(c.x);
    h.y = soy * tanha(c.y);
}

// ---------------- weight prep (interleaved [k][up][gate][2], 0.5 prescale on i/f/o) ----------------
__global__ void prep1(const float* wfih, const float* wfhh, const float* bfih, const float* bfhh,
                      const float* wbih, const float* wbhh, const float* bbih, const float* bbhh) {
    int idx = blockIdx.x * blockDim.x + threadIdx.x;
    if (idx < 2 * 80 * 280) {
        int d = idx / 22400, rem = idx % 22400;
        int k = rem / 280, j = rem % 280;
        int up = j / 8, g = (j / 2) % 4, e = j & 1;
        int u = up * 2 + e, row = g * 70 + u;
        const float* wih = d ? wbih : wfih;
        const float* whh = d ? wbhh : wfhh;
        float v = (k < 10) ? wih[row * 10 + k] : whh[row * 70 + (k - 10)];
        if (g != 2) v *= 0.5f;
        dW1g[idx] = v;
    }
    if (idx < 2 * 280) {
        int d = idx / 280, j = idx % 280;
        int up = j / 8, g = (j / 2) % 4, e = j & 1;
        int u = up * 2 + e, row = g * 70 + u;
        const float* bih = d ? bbih : bfih;
        const float* bhh = d ? bbhh : bfhh;
        float v = bih[row] + bhh[row];
        if (g != 2) v *= 0.5f;
        dB1g[idx] = v;
    }
}

__global__ void prep2(const float* wfih, const float* wfhh, const float* bfih, const float* bfhh,
                      const float* wbih, const float* wbhh, const float* bbih, const float* bbhh) {
    int idx = blockIdx.x * blockDim.x + threadIdx.x;
    if (idx < 2 * 161 * 88) {
        int d = idx / (161 * 88), rem = idx % (161 * 88);
        int k = rem / 88, j = rem % 88;
        int up = j / 8, g = (j / 2) % 4, e = j & 1;
        int u = up * 2 + e;
        float v = 0.f;
        if (u < 21) {
            int row = g * 21 + u;
            const float* wih = d ? wbih : wfih;
            const float* whh = d ? wbhh : wfhh;
            v = (k < 140) ? wih[row * 140 + k] : whh[row * 21 + (k - 140)];
            if (g != 2) v *= 0.5f;
        }
        dW2g[idx] = v;
    }
    if (idx < 2 * 88) {
        int d = idx / 88, j = idx % 88;
        int up = j / 8, g = (j / 2) % 4, e = j & 1;
        int u = up * 2 + e;
        float v = 0.f;
        if (u < 21) {
            int row = g * 21 + u;
            const float* bih = d ? bbih : bfih;
            const float* bhh = d ? bbhh : bfhh;
            v = bih[row] + bhh[row];
            if (g != 2) v *= 0.5f;
        }
        dB2g[idx] = v;
    }
}

// ---------------- layer 1: F=10 -> H=70, bidirectional (R12 config) ----------------
// grid (64, 2), 560 threads = 2 k-groups x 280 (rg 0..7 [4 rows] x up 0..34).
// Non-duplicated acts [k][r32]; packed 128-bit reduction [pair][q][4]; staging
// STS moved to phase 1.
__global__ __launch_bounds__(560, 1) void lstm1(const float* __restrict__ x) {
    extern __shared__ float sm[];
    float* sW = sm;                  // 22400
    float* sB = sW + 22400;          // 280
    float* sA = sB + 280;            // 2 * 2560  ([k80][r32] per buffer)
    float* sRed = sA + 5120;         // 2 grp * (2 rows * 2 gp * 280 q * 4) = 8960
    const int dir = blockIdx.y, bblk = blockIdx.x;
    const int b0 = bblk * 32;
    const int tid = threadIdx.x;

    const float* gW = dW1g + dir * 22400;
    for (int i = tid; i < 22400; i += 560) sW[i] = gW[i];
    if (tid < 280) sB[tid] = dB1g[dir * 280 + tid];
    for (int i = tid; i < 70 * 32; i += 560) sA[10 * 32 + i] = 0.f;   // h-region buf0

    const int grp = (tid >= 280) ? 1 : 0;
    const int q = tid - 280 * grp;
    const int rg = q & 7, up = q >> 3;
    const int r0 = rg * 4, u0 = up * 2;
    const int rown = r0 + 2 * grp;   // owned rows: rown, rown+1
    const int jo = 2 * grp;          // owned acc idx
    const int jn = 2 - 2 * grp;      // non-owned acc idx

    // stage x(t0) into buffer 0 (non-dup: 1 float per thread, tid<320)
    const int xrow = tid / 10, xf = tid % 10;
    const bool hasx = tid < 320;
    if (hasx) sA[xf * 32 + xrow] = x[((b0 + xrow) * TT + (dir ? TT - 1 : 0)) * 10 + xf];
    float xr = 0.f;
    if (hasx) xr = x[((b0 + xrow) * TT + (dir ? TT - 2 : 1)) * 10 + xf];

    float2 c[2];
    c[0] = make_float2(0.f, 0.f);
    c[1] = make_float2(0.f, 0.f);
    const float* pw = sW + grp * 40 * 280 + up * 8;
    float* sRW = sRed + grp * 4480;            // [pair(2rows x 2gp)][q][4]
    const float* sRR = sRed + (1 - grp) * 4480;
    __syncthreads();

    float2 bf[4];
#pragma unroll
    for (int g = 0; g < 4; g++) bf[g] = *(const float2*)&sB[up * 8 + g * 2];

    int p = 0;
    for (int s = 0; s < TT; s++) {
        const int t = dir ? TT - 1 - s : s;
        const float* pa = sA + p * 2560 + grp * 1280 + r0;
        float* nb = sA + (p ^ 1) * 2560;

        ull acc[4][4];
#pragma unroll
        for (int r = 0; r < 4; r++)
#pragma unroll
            for (int g = 0; g < 4; g++) acc[r][g] = 0ull;

#pragma unroll 8
        for (int k = 0; k < 40; k++) {
            float4 av = *(const float4*)(pa + k * 32);          // rows r0..r0+3 (1 wf)
            ull a0 = pk2(av.x), a1 = pk2(av.y), a2 = pk2(av.z), a3 = pk2(av.w);
            ulonglong2 w01 = *(const ulonglong2*)(pw + k * 280);       // gates 0,1 (bcast)
            ulonglong2 w23 = *(const ulonglong2*)(pw + k * 280 + 4);   // gates 2,3 (bcast)
            fma2(acc[0][0], a0, w01.x); fma2(acc[0][1], a0, w01.y);
            fma2(acc[0][2], a0, w23.x); fma2(acc[0][3], a0, w23.y);
            fma2(acc[1][0], a1, w01.x); fma2(acc[1][1], a1, w01.y);
            fma2(acc[1][2], a1, w23.x); fma2(acc[1][3], a1, w23.y);
            fma2(acc[2][0], a2, w01.x); fma2(acc[2][1], a2, w01.y);
            fma2(acc[2][2], a2, w23.x); fma2(acc[2][3], a2, w23.y);
            fma2(acc[3][0], a3, w01.x); fma2(acc[3][1], a3, w01.y);
            fma2(acc[3][2], a3, w23.x); fma2(acc[3][3], a3, w23.y);
        }

        // phase 1: stage x(t+1) into nb (readers finished a barrier ago)
        if (hasx && s + 1 < TT) nb[xf * 32 + xrow] = xr;

        // donate non-owned 2 rows: 4 STS.128, [pair][q][4] (16B-aligned)
        *(ulonglong2*)&sRW[(0 * 280 + q) * 4] = make_ulonglong2(acc[jn][0], acc[jn][1]);
        *(ulonglong2*)&sRW[(1 * 280 + q) * 4] = make_ulonglong2(acc[jn][2], acc[jn][3]);
        *(ulonglong2*)&sRW[(2 * 280 + q) * 4] = make_ulonglong2(acc[jn + 1][0], acc[jn + 1][1]);
        *(ulonglong2*)&sRW[(3 * 280 + q) * 4] = make_ulonglong2(acc[jn + 1][2], acc[jn + 1][3]);
        __syncthreads();

        float2 hv[2];
#pragma unroll
        for (int jj = 0; jj < 2; jj++) {
            ulonglong2 p01 = *(const ulonglong2*)&sRR[((jj * 2 + 0) * 280 + q) * 4];
            ulonglong2 p23 = *(const ulonglong2*)&sRR[((jj * 2 + 1) * 280 + q) * 4];
            float2 y0 = up2(acc[jo + jj][0]), d0 = up2(p01.x);
            float2 y1 = up2(acc[jo + jj][1]), d1 = up2(p01.y);
            float2 y2 = up2(acc[jo + jj][2]), d2 = up2(p23.x);
            float2 y3 = up2(acc[jo + jj][3]), d3 = up2(p23.y);
            y0.x += d0.x + bf[0].x; y0.y += d0.y + bf[0].y;
            y1.x += d1.x + bf[1].x; y1.y += d1.y + bf[1].y;
            y2.x += d2.x + bf[2].x; y2.y += d2.y + bf[2].y;
            y3.x += d3.x + bf[3].x; y3.y += d3.y + bf[3].y;
            lstm_act(y0, y1, y2, y3, c[jj], hv[jj]);
        }

        // h(t) -> other buffer (non-dup) + global blocked-transposed
        *(float2*)&nb[(10 + u0) * 32 + rown] = make_float2(hv[0].x, hv[1].x);
        *(float2*)&nb[(11 + u0) * 32 + rown] = make_float2(hv[0].y, hv[1].y);
        {
            size_t gb = ((size_t)(bblk * TT + t) * 140 + dir * 70 + u0) * 32 + rown;
            *(float2*)&dH1T[gb]      = make_float2(hv[0].x, hv[1].x);
            *(float2*)&dH1T[gb + 32] = make_float2(hv[0].y, hv[1].y);
        }
        // prefetch x(t+2)
        if (hasx && s + 2 < TT) {
            int tn = dir ? TT - 3 - s : s + 2;
            xr = x[((b0 + xrow) * TT + tn) * 10 + xf];
        }
        __syncthreads();
        p ^= 1;
    }
}

// ---------------- layer 2: 140 -> H=21 (pad 22), bidirectional (R12 config) ----------------
// grid (64, 2), 352 threads = 4 k-groups x 88 (rg 0..7 [4 rows] x up 0..10).
// 4 rows/thread (3 LDS / 16 FFMA2); packed 128-bit 3-donor reduction; staging
// STS moved to phase 1.
#define L2_KLOOP(KN)                                                          \
    _Pragma("unroll 8")                                                       \
    for (int k = 0; k < (KN); k++) {                                          \
        float4 av = *(const float4*)(pa + k * 32);                            \
        ull a0 = pk2(av.x), a1 = pk2(av.y), a2 = pk2(av.z), a3 = pk2(av.w);   \
        ulonglong2 w01 = *(const ulonglong2*)(pw + k * 88);                   \
        ulonglong2 w23 = *(const ulonglong2*)(pw + k * 88 + 4);               \
        fma2(acc[0][0], a0, w01.x); fma2(acc[0][1], a0, w01.y);               \
        fma2(acc[0][2], a0, w23.x); fma2(acc[0][3], a0, w23.y);               \
        fma2(acc[1][0], a1, w01.x); fma2(acc[1][1], a1, w01.y);               \
        fma2(acc[1][2], a1, w23.x); fma2(acc[1][3], a1, w23.y);               \
        fma2(acc[2][0], a2, w01.x); fma2(acc[2][1], a2, w01.y);               \
        fma2(acc[2][2], a2, w23.x); fma2(acc[2][3], a2, w23.y);               \
        fma2(acc[3][0], a3, w01.x); fma2(acc[3][1], a3, w01.y);               \
        fma2(acc[3][2], a3, w23.x); fma2(acc[3][3], a3, w23.y);               \
    }

// sRed float index: [row j(4)][donor slot(3)][gatepair(2)][q(88)][4] = 8448
#define SRED(j, sl, gp, q) (((((j) * 3 + (sl)) * 2 + (gp)) * 88 + (q)) * 4)

__global__ __launch_bounds__(352, 1) void lstm2() {
    extern __shared__ float sm[];
    float* sW = sm;                  // 14168
    float* sB = sW + 14168;          // 88
    float* sA = sB + 88;             // 2 * 5152  ([k161][r32] per buffer)
    float* sRed = sA + 10304;        // 8448
    const int dir = blockIdx.y, bblk = blockIdx.x;
    const int tid = threadIdx.x;

    const float* gW = dW2g + dir * 14168;
    for (int i = tid; i < 14168; i += 352) sW[i] = gW[i];
    if (tid < 88) sB[tid] = dB2g[dir * 88 + tid];
    for (int i = tid; i < 21 * 32; i += 352) sA[140 * 32 + i] = 0.f;   // h-region buf0

    // stage h1(t0): 1120 float4 contiguous
    {
        int t0 = dir ? TT - 1 : 0;
        const float4* src = (const float4*)&dH1T[(size_t)(bblk * TT + t0) * 4480];
        float4* dst = (float4*)sA;
#pragma unroll
        for (int j = 0; j < 4; j++) {
            int i = tid + j * 352;
            if (i < 1120) dst[i] = src[i];
        }
    }

    const int grp = tid / 88;
    const int q = tid - 88 * grp;
    const int rg = q & 7, up = q >> 3;
    const int r0 = rg * 4, u0 = up * 2;
    const int rown = r0 + grp;       // owned row

    float2 c = make_float2(0.f, 0.f);
    const int kbeg = grp * 40;
    const float* pw = sW + kbeg * 88 + up * 8;

    // prefetch h1(t1)
    float4 pf[4];
    {
        int t1 = dir ? TT - 2 : 1;
        const float4* src = (const float4*)&dH1T[(size_t)(bblk * TT + t1) * 4480];
#pragma unroll
        for (int j = 0; j < 4; j++) {
            int i = tid + j * 352;
            if (i < 1120) pf[j] = src[i];
        }
    }
    __syncthreads();

    float2 bf[4];
#pragma unroll
    for (int g = 0; g < 4; g++) bf[g] = *(const float2*)&sB[up * 8 + g * 2];

    int p = 0;
    for (int s = 0; s < TT; s++) {
        const int t = dir ? TT - 1 - s : s;
        const float* pa = sA + p * 5152 + kbeg * 32 + r0;
        float* nb = sA + (p ^ 1) * 5152;

        ull acc[4][4];
#pragma unroll
        for (int r = 0; r < 4; r++)
#pragma unroll
            for (int g = 0; g < 4; g++) acc[r][g] = 0ull;

        if (grp == 3) { L2_KLOOP(41) } else { L2_KLOOP(40) }

        // phase 1: stage h1(t+1) into nb (readers finished a barrier ago)
        if (s + 1 < TT) {
            float4* dst = (float4*)nb;
#pragma unroll
            for (int j = 0; j < 4; j++) {
                int i = tid + j * 352;
                if (i < 1120) dst[i] = pf[j];
            }
        }

        // donate 3 non-owned rows: 6 STS.128 (q-coalesced, 16B-aligned)
#pragma unroll
        for (int jj = 0; jj < 4; jj++) {
            if (jj != grp) {
                int sl = grp - ((grp > jj) ? 1 : 0);
                *(ulonglong2*)&sRed[SRED(jj, sl, 0, q)] = make_ulonglong2(acc[jj][0], acc[jj][1]);
                *(ulonglong2*)&sRed[SRED(jj, sl, 1, q)] = make_ulonglong2(acc[jj][2], acc[jj][3]);
            }
        }
        __syncthreads();

        // finalize owned row: own + 3 donations + bias  (6 LDS.128)
        float2 y[4];
#pragma unroll
        for (int g = 0; g < 4; g++) y[g] = up2(acc[grp][g]);
#pragma unroll
        for (int sl = 0; sl < 3; sl++) {
            ulonglong2 p01 = *(const ulonglong2*)&sRed[SRED(grp, sl, 0, q)];
            ulonglong2 p23 = *(const ulonglong2*)&sRed[SRED(grp, sl, 1, q)];
            float2 d0 = up2(p01.x), d1 = up2(p01.y), d2 = up2(p23.x), d3 = up2(p23.y);
            y[0].x += d0.x; y[0].y += d0.y;
            y[1].x += d1.x; y[1].y += d1.y;
            y[2].x += d2.x; y[2].y += d2.y;
            y[3].x += d3.x; y[3].y += d3.y;
        }
#pragma unroll
        for (int g = 0; g < 4; g++) { y[g].x += bf[g].x; y[g].y += bf[g].y; }
        float2 h;
        lstm_act(y[0], y[1], y[2], y[3], c, h);

        // h -> other buffer + global dH2 [bblk][t][42][r32] (coalesced)
        nb[(140 + u0) * 32 + rown] = h.x;
        if (u0 + 1 < 21) nb[(141 + u0) * 32 + rown] = h.y;
        {
            size_t ob = ((size_t)(bblk * TT + t) * 42 + dir * 21 + u0) * 32 + rown;
            dH2[ob] = h.x;
            if (u0 + 1 < 21) dH2[ob + 32] = h.y;
        }

        // prefetch h1(t+2)
        if (s + 2 < TT) {
            int tn = dir ? TT - 3 - s : s + 2;
            const float4* src = (const float4*)&dH1T[(size_t)(bblk * TT + tn) * 4480];
#pragma unroll
            for (int j = 0; j < 4; j++) {
                int i = tid + j * 352;
                if (i < 1120) pf[j] = src[i];
            }
        }
        __syncthreads();
        p ^= 1;
    }
}

// ---------------- dense head: 42 -> relu 30 -> relu 20 -> 1 ----------------
__global__ __launch_bounds__(128) void dense_head(const float* __restrict__ wd1, const float* __restrict__ bd1,
                                                  const float* __restrict__ wd2, const float* __restrict__ bd2,
                                                  const float* __restrict__ wo, const float* __restrict__ bo,
                                                  float* __restrict__ out) {
    __shared__ float sT[4 * 42 * 32];
    __shared__ float sW1[30 * 42], sb1[30], sW2[20 * 30], sb2[20], swo[20], sbo[1];
    const int tid = threadIdx.x;
    const int bblk = blockIdx.x, t0 = blockIdx.y * 4;

    {
        const float4* src = (const float4*)&dH2[(size_t)(bblk * TT + t0) * 1344];
        float4* dst = (float4*)sT;
#pragma unroll
        for (int j = 0; j < 11; j++) {
            int i = tid + j * 128;
            if (i < 1344) dst[i] = src[i];
        }
    }
    for (int i = tid; i < 1260; i += 128) sW1[i] = wd1[i];
    for (int i = tid; i < 600; i += 128) sW2[i] = wd2[i];
    if (tid < 30) sb1[tid] = bd1[tid];
    if (tid < 20) { sb2[tid] = bd2[tid]; swo[tid] = wo[tid]; }
    if (tid == 0) sbo[0] = bo[0];
    __syncthreads();

    const int t = tid >> 5, r = tid & 31;
    float in[42];
#pragma unroll
    for (int u = 0; u < 42; u++) in[u] = sT[(t * 42 + u) * 32 + r];

    float a[30];
#pragma unroll
    for (int j = 0; j < 30; j++) {
        float s = sb1[j];
#pragma unroll
        for (int k = 0; k < 42; k++) s += in[k] * sW1[j * 42 + k];
        a[j] = fmaxf(s, 0.f);
    }
    float o = sbo[0];
#pragma unroll
    for (int j = 0; j < 20; j++) {
        float s = sb2[j];
#pragma unroll
        for (int k = 0; k < 30; k++) s += a[k] * sW2[j * 30 + k];
        o += fmaxf(s, 0.f) * swo[j];
    }
    out[(size_t)(bblk * 32 + r) * TT + t0 + t] = o;
}

// ---------------- launch ----------------
extern "C" void kernel_launch(void* const* d_in, const int* in_sizes, int n_in,
                              void* d_out, int out_size) {
    const float* x = (const float*)d_in[0];

    const int smem1 = (22400 + 280 + 2 * 2560 + 8960) * 4;    // 147040 B
    const int smem2 = (14168 + 88 + 2 * 5152 + 8448) * 4;     // 132032 B
    cudaFuncSetAttribute(lstm1, cudaFuncAttributeMaxDynamicSharedMemorySize, smem1);
    cudaFuncSetAttribute(lstm2, cudaFuncAttributeMaxDynamicSharedMemorySize, smem2);

    prep1<<<175, 256>>>((const float*)d_in[1], (const float*)d_in[2], (const float*)d_in[3], (const float*)d_in[4],
                        (const float*)d_in[5], (const float*)d_in[6], (const float*)d_in[7], (const float*)d_in[8]);
    prep2<<<111, 256>>>((const float*)d_in[9], (const float*)d_in[10], (const float*)d_in[11], (const float*)d_in[12],
                        (const float*)d_in[13], (const float*)d_in[14], (const float*)d_in[15], (const float*)d_in[16]);

    lstm1<<<dim3(64, 2), 560, smem1>>>(x);
    lstm2<<<dim3(64, 2), 352, smem2>>>();

    dense_head<<<dim3(64, 84), 128>>>((const float*)d_in[17], (const float*)d_in[18],
                                      (const float*)d_in[19], (const float*)d_in[20],
                                      (const float*)d_in[21], (const float*)d_in[22],
                                      (float*)d_out);
}

// round 17
// speedup vs baseline: 1.2007x; 1.0194x over previous
#include <cuda_runtime.h>

#define TT 336

// ---------------- device scratch ----------------
__device__ float dW1g[2 * 80 * 280];        // [dir][k][up(35)][gate(4)][2], i/f/o prescaled 0.5
__device__ float dB1g[2 * 280];             // [dir][up][gate][2]
__device__ float dW2x[2 * 140 * 88];        // [dir][k140][u22][g4]  (x-part, prescaled)
__device__ float dW2h[2 * 21 * 88];         // [dir][k21][u22][g4]   (h-part, prescaled)
__device__ float dB2n[2 * 88];              // [dir][u22][g4]        (prescaled)
__device__ float dH1T[64 * 336 * 140 * 32]; // [bblk][t][k(140)][r(32)]
__device__ float dXG[(size_t)64 * 336 * 2 * 704 * 4];  // [bblk][t][dir][u22*32r][g4] : xg+bias
__device__ float dH2[64 * 336 * 42 * 32];   // [bblk][t][u(42)][r(32)]

typedef unsigned long long ull;

// ---------------- f32x2 helpers ----------------
__device__ __forceinline__ ull pk2(float v) {
    ull r;
    asm("mov.b64 %0, {%1, %1};" : "=l"(r) : "f"(v));
    return r;
}
__device__ __forceinline__ ull pk2p(float x, float y) {
    ull r;
    asm("mov.b64 %0, {%1, %2};" : "=l"(r) : "f"(x), "f"(y));
    return r;
}
__device__ __forceinline__ float2 up2(ull v) {
    float2 r;
    asm("mov.b64 {%0, %1}, %2;" : "=f"(r.x), "=f"(r.y) : "l"(v));
    return r;
}
__device__ __forceinline__ void fma2(ull& d, ull a, ull b) {
    asm("fma.rn.f32x2 %0, %1, %2, %3;" : "=l"(d) : "l"(a), "l"(b), "l"(d));
}
__device__ __forceinline__ float tanha(float x) {
    float y;
    asm("tanh.approx.f32 %0, %1;" : "=f"(y) : "f"(x));
    return y;
}
// i/f/o pre-acts prescaled by 0.5 -> sigmoid(z) = 0.5 + 0.5*tanh(z/2)
__device__ __forceinline__ void lstm_act(float2 yi, float2 yf, float2 yg, float2 yo,
                                         float2& c, float2& h) {
    float six = 0.5f + 0.5f * tanha(yi.x), siy = 0.5f + 0.5f * tanha(yi.y);
    float sfx = 0.5f + 0.5f * tanha(yf.x), sfy = 0.5f + 0.5f * tanha(yf.y);
    float tgx = tanha(yg.x), tgy = tanha(yg.y);
    float sox = 0.5f + 0.5f * tanha(yo.x), soy = 0.5f + 0.5f * tanha(yo.y);
    c.x = sfx * c.x + six * tgx;
    c.y = sfy * c.y + siy * tgy;
    h.x = sox * tanha(c.x);
    h.y = soy * tanha(c.y);
}

// ---------------- weight prep ----------------
__global__ void prep1(const float* wfih, const float* wfhh, const float* bfih, const float* bfhh,
                      const float* wbih, const float* wbhh, const float* bbih, const float* bbhh) {
    int idx = blockIdx.x * blockDim.x + threadIdx.x;
    if (idx < 2 * 80 * 280) {
        int d = idx / 22400, rem = idx % 22400;
        int k = rem / 280, j = rem % 280;
        int up = j / 8, g = (j / 2) % 4, e = j & 1;
        int u = up * 2 + e, row = g * 70 + u;
        const float* wih = d ? wbih : wfih;
        const float* whh = d ? wbhh : wfhh;
        float v = (k < 10) ? wih[row * 10 + k] : whh[row * 70 + (k - 10)];
        if (g != 2) v *= 0.5f;
        dW1g[idx] = v;
    }
    if (idx < 2 * 280) {
        int d = idx / 280, j = idx % 280;
        int up = j / 8, g = (j / 2) % 4, e = j & 1;
        int u = up * 2 + e, row = g * 70 + u;
        const float* bih = d ? bbih : bfih;
        const float* bhh = d ? bbhh : bfhh;
        float v = bih[row] + bhh[row];
        if (g != 2) v *= 0.5f;
        dB1g[idx] = v;
    }
}

// layouts [k][u22][g4]; u>=21 zero; gate order i,f,g,o; 0.5 prescale on i,f,o
__global__ void prep2(const float* wfih, const float* wfhh, const float* bfih, const float* bfhh,
                      const float* wbih, const float* wbhh, const float* bbih, const float* bbhh) {
    int idx = blockIdx.x * blockDim.x + threadIdx.x;
    if (idx < 2 * 140 * 88) {
        int d = idx / 12320, rem = idx % 12320;
        int k = rem / 88, j = rem % 88;
        int u = j / 4, g = j % 4;
        float v = 0.f;
        if (u < 21) {
            const float* wih = d ? wbih : wfih;
            v = wih[(g * 21 + u) * 140 + k];
            if (g != 2) v *= 0.5f;
        }
        dW2x[idx] = v;
    }
    if (idx < 2 * 21 * 88) {
        int d = idx / 1848, rem = idx % 1848;
        int k = rem / 88, j = rem % 88;
        int u = j / 4, g = j % 4;
        float v = 0.f;
        if (u < 21) {
            const float* whh = d ? wbhh : wfhh;
            v = whh[(g * 21 + u) * 21 + k];
            if (g != 2) v *= 0.5f;
        }
        dW2h[idx] = v;
    }
    if (idx < 2 * 88) {
        int d = idx / 88, j = idx % 88;
        int u = j / 4, g = j % 4;
        float v = 0.f;
        if (u < 21) {
            int row = g * 21 + u;
            const float* bih = d ? bbih : bfih;
            const float* bhh = d ? bbhh : bfhh;
            v = bih[row] + bhh[row];
            if (g != 2) v *= 0.5f;
        }
        dB2n[idx] = v;
    }
}

// ---------------- layer 1: F=10 -> H=70, bidirectional (R15, unchanged) ----------------
__global__ __launch_bounds__(560, 1) void lstm1(const float* __restrict__ x) {
    extern __shared__ float sm[];
    float* sW = sm;                  // 22400
    float* sB = sW + 22400;          // 280
    float* sA = sB + 280;            // 2 * 2560  ([k80][r32] per buffer)
    float* sRed = sA + 5120;         // 8960
    const int dir = blockIdx.y, bblk = blockIdx.x;
    const int b0 = bblk * 32;
    const int tid = threadIdx.x;

    const float* gW = dW1g + dir * 22400;
    for (int i = tid; i < 22400; i += 560) sW[i] = gW[i];
    if (tid < 280) sB[tid] = dB1g[dir * 280 + tid];
    for (int i = tid; i < 70 * 32; i += 560) sA[10 * 32 + i] = 0.f;

    const int grp = (tid >= 280) ? 1 : 0;
    const int q = tid - 280 * grp;
    const int rg = q & 7, up = q >> 3;
    const int r0 = rg * 4, u0 = up * 2;
    const int rown = r0 + 2 * grp;
    const int jo = 2 * grp;
    const int jn = 2 - 2 * grp;

    const int xrow = tid / 10, xf = tid % 10;
    const bool hasx = tid < 320;
    if (hasx) sA[xf * 32 + xrow] = x[((b0 + xrow) * TT + (dir ? TT - 1 : 0)) * 10 + xf];
    float xr = 0.f;
    if (hasx) xr = x[((b0 + xrow) * TT + (dir ? TT - 2 : 1)) * 10 + xf];

    float2 c[2];
    c[0] = make_float2(0.f, 0.f);
    c[1] = make_float2(0.f, 0.f);
    const float* pw = sW + grp * 40 * 280 + up * 8;
    float* sRW = sRed + grp * 4480;
    const float* sRR = sRed + (1 - grp) * 4480;
    __syncthreads();

    float2 bf[4];
#pragma unroll
    for (int g = 0; g < 4; g++) bf[g] = *(const float2*)&sB[up * 8 + g * 2];

    int p = 0;
    for (int s = 0; s < TT; s++) {
        const int t = dir ? TT - 1 - s : s;
        const float* pa = sA + p * 2560 + grp * 1280 + r0;
        float* nb = sA + (p ^ 1) * 2560;

        ull acc[4][4];
#pragma unroll
        for (int r = 0; r < 4; r++)
#pragma unroll
            for (int g = 0; g < 4; g++) acc[r][g] = 0ull;

#pragma unroll 8
        for (int k = 0; k < 40; k++) {
            float4 av = *(const float4*)(pa + k * 32);
            ull a0 = pk2(av.x), a1 = pk2(av.y), a2 = pk2(av.z), a3 = pk2(av.w);
            ulonglong2 w01 = *(const ulonglong2*)(pw + k * 280);
            ulonglong2 w23 = *(const ulonglong2*)(pw + k * 280 + 4);
            fma2(acc[0][0], a0, w01.x); fma2(acc[0][1], a0, w01.y);
            fma2(acc[0][2], a0, w23.x); fma2(acc[0][3], a0, w23.y);
            fma2(acc[1][0], a1, w01.x); fma2(acc[1][1], a1, w01.y);
            fma2(acc[1][2], a1, w23.x); fma2(acc[1][3], a1, w23.y);
            fma2(acc[2][0], a2, w01.x); fma2(acc[2][1], a2, w01.y);
            fma2(acc[2][2], a2, w23.x); fma2(acc[2][3], a2, w23.y);
            fma2(acc[3][0], a3, w01.x); fma2(acc[3][1], a3, w01.y);
            fma2(acc[3][2], a3, w23.x); fma2(acc[3][3], a3, w23.y);
        }

        if (hasx && s + 1 < TT) nb[xf * 32 + xrow] = xr;

        *(ulonglong2*)&sRW[(0 * 280 + q) * 4] = make_ulonglong2(acc[jn][0], acc[jn][1]);
        *(ulonglong2*)&sRW[(1 * 280 + q) * 4] = make_ulonglong2(acc[jn][2], acc[jn][3]);
        *(ulonglong2*)&sRW[(2 * 280 + q) * 4] = make_ulonglong2(acc[jn + 1][0], acc[jn + 1][1]);
        *(ulonglong2*)&sRW[(3 * 280 + q) * 4] = make_ulonglong2(acc[jn + 1][2], acc[jn + 1][3]);
        __syncthreads();

        float2 hv[2];
#pragma unroll
        for (int jj = 0; jj < 2; jj++) {
            ulonglong2 p01 = *(const ulonglong2*)&sRR[((jj * 2 + 0) * 280 + q) * 4];
            ulonglong2 p23 = *(const ulonglong2*)&sRR[((jj * 2 + 1) * 280 + q) * 4];
            float2 y0 = up2(acc[jo + jj][0]), d0 = up2(p01.x);
            float2 y1 = up2(acc[jo + jj][1]), d1 = up2(p01.y);
            float2 y2 = up2(acc[jo + jj][2]), d2 = up2(p23.x);
            float2 y3 = up2(acc[jo + jj][3]), d3 = up2(p23.y);
            y0.x += d0.x + bf[0].x; y0.y += d0.y + bf[0].y;
            y1.x += d1.x + bf[1].x; y1.y += d1.y + bf[1].y;
            y2.x += d2.x + bf[2].x; y2.y += d2.y + bf[2].y;
            y3.x += d3.x + bf[3].x; y3.y += d3.y + bf[3].y;
            lstm_act(y0, y1, y2, y3, c[jj], hv[jj]);
        }

        *(float2*)&nb[(10 + u0) * 32 + rown] = make_float2(hv[0].x, hv[1].x);
        *(float2*)&nb[(11 + u0) * 32 + rown] = make_float2(hv[0].y, hv[1].y);
        {
            size_t gb = ((size_t)(bblk * TT + t) * 140 + dir * 70 + u0) * 32 + rown;
            *(float2*)&dH1T[gb]      = make_float2(hv[0].x, hv[1].x);
            *(float2*)&dH1T[gb + 32] = make_float2(hv[0].y, hv[1].y);
        }
        if (hasx && s + 2 < TT) {
            int tn = dir ? TT - 3 - s : s + 2;
            xr = x[((b0 + xrow) * TT + tn) * 10 + xf];
        }
        __syncthreads();
        p ^= 1;
    }
}

// ---------------- xgemm: xg2[b,t] = h1[b,t] @ W2x^T + bias (time-parallel) ----------------
// grid (64, 42, 2): (bblk, 8-t tile, dir). 352 threads = (ue 0..21) x (rp 0..15, 2 rows).
// Warp spans 2 ue x 16 rp: weight LDS.128 2-addr bcast, act LDS.64 1 wf.
// Inner loop: 6 issues / 8 fma-cyc (fma-bound). Output coalesced STG.128.
__global__ __launch_bounds__(352, 2) void xgemm() {
    extern __shared__ float sm[];
    float* sW = sm;                  // 12320
    float* sA = sm + 12320;          // 2 * 4480
    const int bblk = blockIdx.x, tt0 = blockIdx.y * 8, dir = blockIdx.z;
    const int tid = threadIdx.x;

    const float* gW = dW2x + dir * 12320;
    for (int i = tid; i < 12320; i += 352) sW[i] = gW[i];

    const int rp = tid & 15, ue = tid >> 4;
    const int r0 = rp * 2;

    ulonglong2 binit;
    {
        float4 b = *(const float4*)&dB2n[dir * 88 + ue * 4];
        binit.x = pk2p(b.x, b.y);
        binit.y = pk2p(b.z, b.w);
    }

    // stage act(t0)
    {
        const float4* src = (const float4*)&dH1T[(size_t)(bblk * TT + tt0) * 4480];
        float4* dst = (float4*)sA;
#pragma unroll
        for (int j = 0; j < 4; j++) {
            int i = tid + j * 352;
            if (i < 1120) dst[i] = src[i];
        }
    }
    __syncthreads();

    int p = 0;
    for (int tt = 0; tt < 8; tt++) {
        const int t = tt0 + tt;
        float4 pf[4];
        if (tt < 7) {
            const float4* src = (const float4*)&dH1T[(size_t)(bblk * TT + t + 1) * 4480];
#pragma unroll
            for (int j = 0; j < 4; j++) {
                int i = tid + j * 352;
                if (i < 1120) pf[j] = src[i];
            }
        }

        ull a00 = binit.x, a01 = binit.y, a10 = binit.x, a11 = binit.y;
        const float* pa = sA + p * 4480 + r0;
        const float* pw = sW + ue * 4;
#pragma unroll 10
        for (int k = 0; k < 140; k++) {
            float2 a = *(const float2*)(pa + k * 32);
            ull v0 = pk2(a.x), v1 = pk2(a.y);
            ulonglong2 w = *(const ulonglong2*)(pw + k * 88);   // {w_i,w_f},{w_g,w_o}
            fma2(a00, v0, w.x); fma2(a01, v0, w.y);
            fma2(a10, v1, w.x); fma2(a11, v1, w.y);
        }
        {
            size_t ob = (((size_t)(bblk * TT + t) * 2 + dir) * 704 + ue * 32 + r0) * 4;
            float2 x0 = up2(a00), x1 = up2(a01), x2 = up2(a10), x3 = up2(a11);
            *(float4*)&dXG[ob]     = make_float4(x0.x, x0.y, x1.x, x1.y);
            *(float4*)&dXG[ob + 4] = make_float4(x2.x, x2.y, x3.x, x3.y);
        }
        if (tt < 7) {
            float4* dst = (float4*)(sA + (p ^ 1) * 4480);
#pragma unroll
            for (int j = 0; j < 4; j++) {
                int i = tid + j * 352;
                if (i < 1120) dst[i] = pf[j];
            }
        }
        __syncthreads();
        p ^= 1;
    }
}

// ---------------- layer 2 recurrence: K=21 only ----------------
// grid (64, 2), 704 threads = (ue 0..21) x (r 0..31). Warp = one ue: weight
// LDS.128 single-addr broadcast, act LDS.32 1-wf, xg via 1 coalesced LDG.128.
// No reduction, no k-split, ONE barrier per step.
__global__ __launch_bounds__(704, 1) void lstm2r() {
    __shared__ float sWh[21 * 88];
    __shared__ float sH[2][21 * 32];
    const int bblk = blockIdx.x, dir = blockIdx.y;
    const int tid = threadIdx.x;
    const int r = tid & 31, ue = tid >> 5;

    const float* gW = dW2h + dir * 1848;
    for (int i = tid; i < 1848; i += 704) sWh[i] = gW[i];
    for (int i = tid; i < 672; i += 704) sH[0][i] = 0.f;

    float4 pfx;
    {
        int t0 = dir ? TT - 1 : 0;
        pfx = *(const float4*)&dXG[(((size_t)(bblk * TT + t0) * 2 + dir) * 704 + ue * 32 + r) * 4];
    }
    float c = 0.f;
    const float* pw = sWh + ue * 4;
    __syncthreads();

    int p = 0;
    for (int s = 0; s < TT; s++) {
        const int t = dir ? TT - 1 - s : s;
        ull acc0 = pk2p(pfx.x, pfx.y);   // (y_i, y_f)
        ull acc1 = pk2p(pfx.z, pfx.w);   // (y_g, y_o)
        const float* pa = &sH[p][r];
#pragma unroll
        for (int k = 0; k < 21; k++) {
            ull av = pk2(pa[k * 32]);
            ulonglong2 w = *(const ulonglong2*)(pw + k * 88);
            fma2(acc0, av, w.x);
            fma2(acc1, av, w.y);
        }
        if (s + 1 < TT) {
            int tn = dir ? TT - 2 - s : s + 1;
            pfx = *(const float4*)&dXG[(((size_t)(bblk * TT + tn) * 2 + dir) * 704 + ue * 32 + r) * 4];
        }

        float2 y01 = up2(acc0), y23 = up2(acc1);
        float si = 0.5f + 0.5f * tanha(y01.x);
        float sf = 0.5f + 0.5f * tanha(y01.y);
        float tg = tanha(y23.x);
        float so = 0.5f + 0.5f * tanha(y23.y);
        c = sf * c + si * tg;
        float h = so * tanha(c);

        if (ue < 21) {
            sH[p ^ 1][ue * 32 + r] = h;
            dH2[((size_t)(bblk * TT + t) * 42 + dir * 21 + ue) * 32 + r] = h;
        }
        __syncthreads();
        p ^= 1;
    }
}

// ---------------- dense head: 42 -> relu 30 -> relu 20 -> 1 (unchanged) ----------------
__global__ __launch_bounds__(128) void dense_head(const float* __restrict__ wd1, const float* __restrict__ bd1,
                                                  const float* __restrict__ wd2, const float* __restrict__ bd2,
                                                  const float* __restrict__ wo, const float* __restrict__ bo,
                                                  float* __restrict__ out) {
    __shared__ float sT[4 * 42 * 32];
    __shared__ float sW1[30 * 42], sb1[30], sW2[20 * 30], sb2[20], swo[20], sbo[1];
    const int tid = threadIdx.x;
    const int bblk = blockIdx.x, t0 = blockIdx.y * 4;

    {
        const float4* src = (const float4*)&dH2[(size_t)(bblk * TT + t0) * 1344];
        float4* dst = (float4*)sT;
#pragma unroll
        for (int j = 0; j < 11; j++) {
            int i = tid + j * 128;
            if (i < 1344) dst[i] = src[i];
        }
    }
    for (int i = tid; i < 1260; i += 128) sW1[i] = wd1[i];
    for (int i = tid; i < 600; i += 128) sW2[i] = wd2[i];
    if (tid < 30) sb1[tid] = bd1[tid];
    if (tid < 20) { sb2[tid] = bd2[tid]; swo[tid] = wo[tid]; }
    if (tid == 0) sbo[0] = bo[0];
    __syncthreads();

    const int t = tid >> 5, r = tid & 31;
    float in[42];
#pragma unroll
    for (int u = 0; u < 42; u++) in[u] = sT[(t * 42 + u) * 32 + r];

    float a[30];
#pragma unroll
    for (int j = 0; j < 30; j++) {
        float s = sb1[j];
#pragma unroll
        for (int k = 0; k < 42; k++) s += in[k] * sW1[j * 42 + k];
        a[j] = fmaxf(s, 0.f);
    }
    float o = sbo[0];
#pragma unroll
    for (int j = 0; j < 20; j++) {
        float s = sb2[j];
#pragma unroll
        for (int k = 0; k < 30; k++) s += a[k] * sW2[j * 30 + k];
        o += fmaxf(s, 0.f) * swo[j];
    }
    out[(size_t)(bblk * 32 + r) * TT + t0 + t] = o;
}

// ---------------- launch ----------------
extern "C" void kernel_launch(void* const* d_in, const int* in_sizes, int n_in,
                              void* d_out, int out_size) {
    const float* x = (const float*)d_in[0];

    const int smem1 = (22400 + 280 + 2 * 2560 + 8960) * 4;    // 147040 B
    const int smemg = (12320 + 2 * 4480) * 4;                 // 85120 B
    cudaFuncSetAttribute(lstm1, cudaFuncAttributeMaxDynamicSharedMemorySize, smem1);
    cudaFuncSetAttribute(xgemm, cudaFuncAttributeMaxDynamicSharedMemorySize, smemg);

    prep1<<<175, 256>>>((const float*)d_in[1], (const float*)d_in[2], (const float*)d_in[3], (const float*)d_in[4],
                        (const float*)d_in[5], (const float*)d_in[6], (const float*)d_in[7], (const float*)d_in[8]);
    prep2<<<97, 256>>>((const float*)d_in[9], (const float*)d_in[10], (const float*)d_in[11], (const float*)d_in[12],
                       (const float*)d_in[13], (const float*)d_in[14], (const float*)d_in[15], (const float*)d_in[16]);

    lstm1<<<dim3(64, 2), 560, smem1>>>(x);
    xgemm<<<dim3(64, 42, 2), 352, smemg>>>();
    lstm2r<<<dim3(64, 2), 704>>>();

    dense_head<<<dim3(64, 84), 128>>>((const float*)d_in[17], (const float*)d_in[18],
                                      (const float*)d_in[19], (const float*)d_in[20],
                                      (const float*)d_in[21], (const float*)d_in[22],
                                      (float*)d_out);
}